// round 13
// baseline (speedup 1.0000x reference)
#include <cuda_runtime.h>
#include <math.h>

#define NMAX 100000
#define EMAX 1700000
#define DMAX 64
#define SCAN_CHUNK 512

// ---------------- scratch (device globals; no allocation allowed) ----------
__device__ int   g_is64;
__device__ int   g_cnt[NMAX];
__device__ int   g_off[NMAX + 1];
__device__ int   g_part[1024];
__device__ int   g_esrc[EMAX];
__device__ float g_e[EMAX];
__device__ __align__(16) float g_h[(size_t)NMAX * DMAX];
__device__ __align__(16) float g_bufA[(size_t)NMAX * DMAX];
__device__ float g_asA[NMAX];
__device__ float g_adA[NMAX];
__device__ float g_asB[NMAX];
__device__ float g_adB[NMAX];

// ---------------- dtype detection ----------------
__global__ void detect_kernel(const unsigned int* __restrict__ w) {
    if (threadIdx.x != 0 || blockIdx.x != 0) return;
    int ok64 = 1;
#pragma unroll
    for (int i = 1; i < 128; i += 2) ok64 &= (w[i] == 0u);
    g_is64 = ok64;
}

__device__ __forceinline__ int load_idx(const void* eiv, long long pos) {
    if (g_is64) return (int)((const long long*)eiv)[pos];
    return ((const int*)eiv)[pos];
}

__device__ __forceinline__ int clampN(int v, int N) {
    return (v < 0) ? 0 : (v >= N ? N - 1 : v);
}

// ---------------- CSR build ----------------
__global__ void zero_cnt_kernel(int N) {
    int i = blockIdx.x * blockDim.x + threadIdx.x;
    if (i < N) g_cnt[i] = 0;
}

__global__ void hist_kernel(const void* __restrict__ eiv, int E, int Etot, int N) {
    int i = blockIdx.x * blockDim.x + threadIdx.x;
    if (i >= Etot) return;
    int d = (i < E) ? clampN(load_idx(eiv, (long long)E + i), N) : (i - E);
    atomicAdd(&g_cnt[d], 1);
}

__global__ void scan_reduce_kernel(int N) {
    __shared__ int sh[256];
    int b = blockIdx.x, t = threadIdx.x;
    int i0 = b * SCAN_CHUNK + t * 2;
    int s = 0;
    if (i0     < N) s += g_cnt[i0];
    if (i0 + 1 < N) s += g_cnt[i0 + 1];
    sh[t] = s;
    __syncthreads();
#pragma unroll
    for (int o = 128; o; o >>= 1) {
        if (t < o) sh[t] += sh[t + o];
        __syncthreads();
    }
    if (t == 0) g_part[b] = sh[0];
}

__global__ void scan_partials_kernel(int B, int N) {
    __shared__ int sh[1024];
    int t = threadIdx.x;
    int v = (t < B) ? g_part[t] : 0;
    sh[t] = v;
    __syncthreads();
#pragma unroll
    for (int o = 1; o < 1024; o <<= 1) {
        int u = (t >= o) ? sh[t - o] : 0;
        __syncthreads();
        sh[t] += u;
        __syncthreads();
    }
    if (t < B) g_part[t] = sh[t] - v;
    if (t == 1023) g_off[N] = sh[1023];
}

__global__ void scan_final_kernel(int N) {
    __shared__ int sh[256];
    int b = blockIdx.x, t = threadIdx.x;
    int i0 = b * SCAN_CHUNK + t * 2;
    int c0 = (i0     < N) ? g_cnt[i0]     : 0;
    int c1 = (i0 + 1 < N) ? g_cnt[i0 + 1] : 0;
    int s = c0 + c1;
    sh[t] = s;
    __syncthreads();
#pragma unroll
    for (int o = 1; o < 256; o <<= 1) {
        int u = (t >= o) ? sh[t - o] : 0;
        __syncthreads();
        sh[t] += u;
        __syncthreads();
    }
    int base = g_part[b] + sh[t] - s;
    if (i0 < N)     { g_off[i0]     = base;      g_cnt[i0]     = base; }
    if (i0 + 1 < N) { g_off[i0 + 1] = base + c0; g_cnt[i0 + 1] = base + c0; }
}

__global__ void scatter_kernel(const void* __restrict__ eiv, int E, int Etot, int N) {
    int i = blockIdx.x * blockDim.x + threadIdx.x;
    if (i >= Etot) return;
    int s, d;
    if (i < E) {
        s = clampN(load_idx(eiv, i), N);
        d = clampN(load_idx(eiv, (long long)E + i), N);
    } else {
        s = d = i - E;
    }
    int p = atomicAdd(&g_cnt[d], 1);
    if (p >= 0 && p < EMAX) g_esrc[p] = s;
}

// ---------------- GEMM layer 0 (128x64 tile, double-buffered) --------------
__global__ __launch_bounds__(256) void gemm_kernel(
    const float* __restrict__ X,
    const float* __restrict__ W,
    const float* __restrict__ a_s, const float* __restrict__ a_d,
    float* __restrict__ as_out, float* __restrict__ ad_out,
    int N, int F, int D)
{
    __shared__ __align__(16) float xs[2][16][132];
    __shared__ __align__(16) float ws[2][16][64];
    __shared__ float as_s[64], ad_s[64];
    int tid  = threadIdx.x;
    int row0 = blockIdx.x * 128;
    int tr = tid >> 4, tc = tid & 15;
    float acc[8][4] = {};
    int f0 = tid * 2;
    int lrow0 = f0 >> 2, lq0 = f0 & 3;
    int lrow1 = (f0 + 1) >> 2, lq1 = (f0 + 1) & 3;
    int wcol = tid & 63, wk0 = (tid >> 6) << 2;
    int gn0 = row0 + lrow0, gn1 = row0 + lrow1;
    const float4* Xr0 = reinterpret_cast<const float4*>(X + (size_t)gn0 * F);
    const float4* Xr1 = reinterpret_cast<const float4*>(X + (size_t)gn1 * F);

    if (tid < 64) {
        as_s[tid] = (tid < D) ? a_s[tid] : 0.f;
        ad_s[tid] = (tid < D) ? a_d[tid] : 0.f;
    }

    int T = F >> 4;
    float4 xv0, xv1;
    float wv[4];
    {
        xv0 = make_float4(0.f,0.f,0.f,0.f); xv1 = xv0;
        if (gn0 < N) xv0 = Xr0[lq0];
        if (gn1 < N) xv1 = Xr1[lq1];
#pragma unroll
        for (int j = 0; j < 4; j++)
            wv[j] = (wcol < D) ? W[(size_t)(wk0 + j) * D + wcol] : 0.f;
    }

    for (int t = 0; t < T; t++) {
        int cur = t & 1;
        xs[cur][lq0 * 4 + 0][lrow0] = xv0.x;
        xs[cur][lq0 * 4 + 1][lrow0] = xv0.y;
        xs[cur][lq0 * 4 + 2][lrow0] = xv0.z;
        xs[cur][lq0 * 4 + 3][lrow0] = xv0.w;
        xs[cur][lq1 * 4 + 0][lrow1] = xv1.x;
        xs[cur][lq1 * 4 + 1][lrow1] = xv1.y;
        xs[cur][lq1 * 4 + 2][lrow1] = xv1.z;
        xs[cur][lq1 * 4 + 3][lrow1] = xv1.w;
#pragma unroll
        for (int j = 0; j < 4; j++)
            ws[cur][wk0 + j][wcol] = wv[j];
        __syncthreads();

        if (t + 1 < T) {
            int k1 = (t + 1) << 4;
            xv0 = make_float4(0.f,0.f,0.f,0.f); xv1 = xv0;
            if (gn0 < N) xv0 = Xr0[(k1 >> 2) + lq0];
            if (gn1 < N) xv1 = Xr1[(k1 >> 2) + lq1];
#pragma unroll
            for (int j = 0; j < 4; j++)
                wv[j] = (wcol < D) ? W[(size_t)(k1 + wk0 + j) * D + wcol] : 0.f;
        }

#pragma unroll
        for (int k = 0; k < 16; k++) {
            float4 a04 = *(const float4*)&xs[cur][k][tr * 8];
            float4 a48 = *(const float4*)&xs[cur][k][tr * 8 + 4];
            float4 b   = *(const float4*)&ws[cur][k][tc * 4];
            acc[0][0] += a04.x * b.x; acc[0][1] += a04.x * b.y; acc[0][2] += a04.x * b.z; acc[0][3] += a04.x * b.w;
            acc[1][0] += a04.y * b.x; acc[1][1] += a04.y * b.y; acc[1][2] += a04.y * b.z; acc[1][3] += a04.y * b.w;
            acc[2][0] += a04.z * b.x; acc[2][1] += a04.z * b.y; acc[2][2] += a04.z * b.z; acc[2][3] += a04.z * b.w;
            acc[3][0] += a04.w * b.x; acc[3][1] += a04.w * b.y; acc[3][2] += a04.w * b.z; acc[3][3] += a04.w * b.w;
            acc[4][0] += a48.x * b.x; acc[4][1] += a48.x * b.y; acc[4][2] += a48.x * b.z; acc[4][3] += a48.x * b.w;
            acc[5][0] += a48.y * b.x; acc[5][1] += a48.y * b.y; acc[5][2] += a48.y * b.z; acc[5][3] += a48.y * b.w;
            acc[6][0] += a48.z * b.x; acc[6][1] += a48.z * b.y; acc[6][2] += a48.z * b.z; acc[6][3] += a48.z * b.w;
            acc[7][0] += a48.w * b.x; acc[7][1] += a48.w * b.y; acc[7][2] += a48.w * b.z; acc[7][3] += a48.w * b.w;
        }
        __syncthreads();
    }

    float sdot[8] = {}, ddot[8] = {};
    int c0 = tc * 4;
#pragma unroll
    for (int i = 0; i < 8; i++) {
        int n = row0 + tr * 8 + i;
        bool ok = (n < N);
#pragma unroll
        for (int j = 0; j < 4; j++) {
            int c = c0 + j;
            if (ok && c < D) g_h[(size_t)n * D + c] = acc[i][j];
            float w = (c < D) ? acc[i][j] : 0.f;
            sdot[i] += w * as_s[c];
            ddot[i] += w * ad_s[c];
        }
    }
#pragma unroll
    for (int o = 8; o; o >>= 1) {
#pragma unroll
        for (int i = 0; i < 8; i++) {
            sdot[i] += __shfl_xor_sync(0xffffffffu, sdot[i], o);
            ddot[i] += __shfl_xor_sync(0xffffffffu, ddot[i], o);
        }
    }
    if (tc == 0) {
#pragma unroll
        for (int i = 0; i < 8; i++) {
            int n = row0 + tr * 8 + i;
            if (n < N) { as_out[n] = sdot[i]; ad_out[n] = ddot[i]; }
        }
    }
}

// ---------------- fused agg + relu + GEMM (layers 1,2) ---------------------
// Block handles 128 dst nodes. Reads dots from as_in/ad_in (previous layer),
// writes next-layer dots to as_out/ad_out (DIFFERENT buffers: no cross-block
// race). sel: 0 = g_h->g_bufA, 1 = g_bufA->g_h.
#define XS2_STRIDE 68
#define FUSED_SMEM ((128 * XS2_STRIDE + 64 * 64) * 4)   // 51200 B

__global__ __launch_bounds__(256) void fused_agg_gemm_kernel(
    int sel, const float* __restrict__ W,
    const float* __restrict__ a_s, const float* __restrict__ a_d,
    const float* __restrict__ as_in, const float* __restrict__ ad_in,
    float* __restrict__ as_out, float* __restrict__ ad_out,
    int N, int D)
{
    extern __shared__ __align__(16) float dsm[];
    float* xs2 = dsm;                         // [128][XS2_STRIDE]
    float* wsm = dsm + 128 * XS2_STRIDE;      // [64][64]
    __shared__ float as_s[64], ad_s[64];

    const float* Hin  = sel ? g_bufA : g_h;
    float*       Hout = sel ? g_h    : g_bufA;
    const float4* H4 = reinterpret_cast<const float4*>(Hin);

    int tid = threadIdx.x, wid = tid >> 5, lane = tid & 31;
    int row0 = blockIdx.x * 128;

    // stage W (pad cols >= D with 0) and attention vectors
    for (int idx = tid; idx < 64 * 64; idx += 256) {
        int k = idx >> 6, c = idx & 63;
        wsm[idx] = (c < D) ? W[(size_t)k * D + c] : 0.f;
    }
    if (tid < 64) {
        as_s[tid] = (tid < D) ? a_s[tid] : 0.f;
        ad_s[tid] = (tid < D) ? a_d[tid] : 0.f;
    }

    // ---- agg phase: warp w handles nodes row0 + w*16 .. +15 ----
    int half = lane >> 4, hl = lane & 15;
    int cc0 = hl * 4;
    for (int j = 0; j < 16; j++) {
        int nl = wid * 16 + j;
        int n = row0 + nl;
        if (n >= N) {
            if (lane < 17) {
                *reinterpret_cast<float4*>(&xs2[nl * XS2_STRIDE + lane * 4]) =
                    make_float4(0.f, 0.f, 0.f, 0.f);
            }
            continue;
        }
        int beg = g_off[n], end = g_off[n + 1];
        float adn = ad_in[n];

        float sum = 0.f;
        for (int p = beg + lane; p < end; p += 32) {
            float v = as_in[g_esrc[p]] + adn;
            v = (v > 0.f) ? v : 0.2f * v;
            float ex = __expf(v);
            g_e[p] = ex;
            sum += ex;
        }
#pragma unroll
        for (int o = 16; o; o >>= 1) sum += __shfl_xor_sync(0xffffffffu, sum, o);
        float inv = 1.f / (sum + 1e-16f);

        float4 acc = make_float4(0.f, 0.f, 0.f, 0.f);
#pragma unroll 2
        for (int p = beg + half; p < end; p += 2) {
            float a = g_e[p] * inv;
            int s = g_esrc[p];
            float4 h = H4[(size_t)s * 16 + hl];
            acc.x += a * h.x; acc.y += a * h.y;
            acc.z += a * h.z; acc.w += a * h.w;
        }
        acc.x += __shfl_xor_sync(0xffffffffu, acc.x, 16);
        acc.y += __shfl_xor_sync(0xffffffffu, acc.y, 16);
        acc.z += __shfl_xor_sync(0xffffffffu, acc.z, 16);
        acc.w += __shfl_xor_sync(0xffffffffu, acc.w, 16);
        if (half == 0) {
            acc.x = fmaxf(acc.x, 0.f); acc.y = fmaxf(acc.y, 0.f);
            acc.z = fmaxf(acc.z, 0.f); acc.w = fmaxf(acc.w, 0.f);
            *reinterpret_cast<float4*>(&xs2[nl * XS2_STRIDE + cc0]) = acc;
        }
    }
    __syncthreads();

    // ---- gemm phase: [128 x 64] @ [64 x D] from smem ----
    int tr = tid >> 4, tc = tid & 15;
    float acc[8][4] = {};
    const float* xrow0 = &xs2[(tr * 8 + 0) * XS2_STRIDE];
#pragma unroll 8
    for (int k = 0; k < 64; k++) {
        float4 b = *(const float4*)&wsm[k * 64 + tc * 4];
        float a0 = xrow0[0 * XS2_STRIDE + k];
        float a1 = xrow0[1 * XS2_STRIDE + k];
        float a2 = xrow0[2 * XS2_STRIDE + k];
        float a3 = xrow0[3 * XS2_STRIDE + k];
        float a4 = xrow0[4 * XS2_STRIDE + k];
        float a5 = xrow0[5 * XS2_STRIDE + k];
        float a6 = xrow0[6 * XS2_STRIDE + k];
        float a7 = xrow0[7 * XS2_STRIDE + k];
        acc[0][0] += a0 * b.x; acc[0][1] += a0 * b.y; acc[0][2] += a0 * b.z; acc[0][3] += a0 * b.w;
        acc[1][0] += a1 * b.x; acc[1][1] += a1 * b.y; acc[1][2] += a1 * b.z; acc[1][3] += a1 * b.w;
        acc[2][0] += a2 * b.x; acc[2][1] += a2 * b.y; acc[2][2] += a2 * b.z; acc[2][3] += a2 * b.w;
        acc[3][0] += a3 * b.x; acc[3][1] += a3 * b.y; acc[3][2] += a3 * b.z; acc[3][3] += a3 * b.w;
        acc[4][0] += a4 * b.x; acc[4][1] += a4 * b.y; acc[4][2] += a4 * b.z; acc[4][3] += a4 * b.w;
        acc[5][0] += a5 * b.x; acc[5][1] += a5 * b.y; acc[5][2] += a5 * b.z; acc[5][3] += a5 * b.w;
        acc[6][0] += a6 * b.x; acc[6][1] += a6 * b.y; acc[6][2] += a6 * b.z; acc[6][3] += a6 * b.w;
        acc[7][0] += a7 * b.x; acc[7][1] += a7 * b.y; acc[7][2] += a7 * b.z; acc[7][3] += a7 * b.w;
    }

    // epilogue: Hout + dots into the OTHER as/ad buffers
    float sdot[8] = {}, ddot[8] = {};
    int c0 = tc * 4;
#pragma unroll
    for (int i = 0; i < 8; i++) {
        int n = row0 + tr * 8 + i;
        bool ok = (n < N);
#pragma unroll
        for (int j = 0; j < 4; j++) {
            int c = c0 + j;
            if (ok && c < D) Hout[(size_t)n * D + c] = acc[i][j];
            float w = (c < D) ? acc[i][j] : 0.f;
            sdot[i] += w * as_s[c];
            ddot[i] += w * ad_s[c];
        }
    }
#pragma unroll
    for (int o = 8; o; o >>= 1) {
#pragma unroll
        for (int i = 0; i < 8; i++) {
            sdot[i] += __shfl_xor_sync(0xffffffffu, sdot[i], o);
            ddot[i] += __shfl_xor_sync(0xffffffffu, ddot[i], o);
        }
    }
    if (tc == 0) {
#pragma unroll
        for (int i = 0; i < 8; i++) {
            int n = row0 + tr * 8 + i;
            if (n < N) { as_out[n] = sdot[i]; ad_out[n] = ddot[i]; }
        }
    }
}

// ---------------- final agg (half-warp, writes d_out) ----------------------
__global__ void agg_final_kernel(
    float* __restrict__ OUT,
    const float* __restrict__ as_in, const float* __restrict__ ad_in,
    int N, int D)
{
    int warp = (blockIdx.x * blockDim.x + threadIdx.x) >> 5;
    int lane = threadIdx.x & 31;
    int nw = (gridDim.x * blockDim.x) >> 5;
    const float4* H4 = reinterpret_cast<const float4*>(g_h);
    int rowst = D >> 2;
    int half = lane >> 4;
    int hl   = lane & 15;
    int c0   = hl * 4;
    bool act = (c0 < D);

    for (int n = warp; n < N; n += nw) {
        int beg = g_off[n], end = g_off[n + 1];
        float adn = ad_in[n];

        float sum = 0.f;
        for (int p = beg + lane; p < end; p += 32) {
            float v = as_in[g_esrc[p]] + adn;
            v = (v > 0.f) ? v : 0.2f * v;
            float ex = __expf(v);
            g_e[p] = ex;
            sum += ex;
        }
#pragma unroll
        for (int o = 16; o; o >>= 1) sum += __shfl_xor_sync(0xffffffffu, sum, o);
        float inv = 1.f / (sum + 1e-16f);

        float4 acc = make_float4(0.f, 0.f, 0.f, 0.f);
#pragma unroll 2
        for (int p = beg + half; p < end; p += 2) {
            float a = g_e[p] * inv;
            int s = g_esrc[p];
            if (act) {
                float4 h = H4[(size_t)s * rowst + hl];
                acc.x += a * h.x;
                acc.y += a * h.y;
                acc.z += a * h.z;
                acc.w += a * h.w;
            }
        }
        acc.x += __shfl_xor_sync(0xffffffffu, acc.x, 16);
        acc.y += __shfl_xor_sync(0xffffffffu, acc.y, 16);
        acc.z += __shfl_xor_sync(0xffffffffu, acc.z, 16);
        acc.w += __shfl_xor_sync(0xffffffffu, acc.w, 16);
        if (half == 0 && act)
            *reinterpret_cast<float4*>(&OUT[(size_t)n * D + c0]) = acc;
    }
}

// ---------------- launch ----------------
extern "C" void kernel_launch(void* const* d_in, const int* in_sizes, int n_in,
                              void* d_out, int out_size)
{
    const float* x     = (const float*)d_in[0];
    const void*  ei    = d_in[1];
    const float* W0    = (const float*)d_in[2];
    const float* asrc0 = (const float*)d_in[3];
    const float* adst0 = (const float*)d_in[4];
    const float* W1    = (const float*)d_in[5];
    const float* asrc1 = (const float*)d_in[6];
    const float* adst1 = (const float*)d_in[7];
    const float* W2    = (const float*)d_in[8];
    const float* asrc2 = (const float*)d_in[9];
    const float* adst2 = (const float*)d_in[10];

    int H    = in_sizes[3];            // 64
    int C    = in_sizes[9];            // 40
    int Fin  = in_sizes[2] / H;        // 256
    int N    = in_sizes[0] / Fin;      // 100000
    int E    = in_sizes[1] / 2;        // 1600000
    int Etot = E + N;
    int SB   = (N + SCAN_CHUNK - 1) / SCAN_CHUNK;

    static cudaStream_t s2 = nullptr;
    static cudaEvent_t ev_fork = nullptr, ev_csr = nullptr;
    static float *asA = nullptr, *adA = nullptr, *asB = nullptr, *adB = nullptr;
    if (!s2) {
        cudaStreamCreateWithFlags(&s2, cudaStreamNonBlocking);
        cudaEventCreateWithFlags(&ev_fork, cudaEventDisableTiming);
        cudaEventCreateWithFlags(&ev_csr, cudaEventDisableTiming);
        cudaFuncSetAttribute(fused_agg_gemm_kernel,
                             cudaFuncAttributeMaxDynamicSharedMemorySize, FUSED_SMEM);
        cudaGetSymbolAddress((void**)&asA, g_asA);
        cudaGetSymbolAddress((void**)&adA, g_adA);
        cudaGetSymbolAddress((void**)&asB, g_asB);
        cudaGetSymbolAddress((void**)&adB, g_adB);
    }

    int gemm_blocks = (N + 127) / 128;
    int wg_blocks   = (N + 7) / 8;

    // fork: CSR build on s2, concurrent with gemm0 on the main stream
    cudaEventRecord(ev_fork, 0);
    cudaStreamWaitEvent(s2, ev_fork, 0);

    detect_kernel<<<1, 32, 0, s2>>>((const unsigned int*)ei);
    zero_cnt_kernel<<<(N + 255) / 256, 256, 0, s2>>>(N);
    hist_kernel<<<(Etot + 255) / 256, 256, 0, s2>>>(ei, E, Etot, N);
    scan_reduce_kernel<<<SB, 256, 0, s2>>>(N);
    scan_partials_kernel<<<1, 1024, 0, s2>>>(SB, N);
    scan_final_kernel<<<SB, 256, 0, s2>>>(N);
    scatter_kernel<<<(Etot + 255) / 256, 256, 0, s2>>>(ei, E, Etot, N);
    cudaEventRecord(ev_csr, s2);

    // layer 0 GEMM (concurrent with CSR build): x -> g_h, dots -> A buffers
    gemm_kernel<<<gemm_blocks, 256>>>(x, W0, asrc0, adst0, asA, adA, N, Fin, H);

    cudaStreamWaitEvent(0, ev_csr, 0);

    // layer 1: agg(g_h, dots A) + relu + @W1 -> g_bufA, dots -> B
    fused_agg_gemm_kernel<<<gemm_blocks, 256, FUSED_SMEM>>>(
        0, W1, asrc1, adst1, asA, adA, asB, adB, N, H);
    // layer 2: agg(g_bufA, dots B) + relu + @W2 -> g_h (stride C), dots -> A
    fused_agg_gemm_kernel<<<gemm_blocks, 256, FUSED_SMEM>>>(
        1, W2, asrc2, adst2, asB, adB, asA, adA, N, C);
    // layer 3 aggregation (dots A) -> d_out
    agg_final_kernel<<<wg_blocks, 256>>>((float*)d_out, asA, adA, N, C);
}

// round 14
// speedup vs baseline: 1.1513x; 1.1513x over previous
#include <cuda_runtime.h>
#include <cuda_bf16.h>
#include <math.h>
#include <stdint.h>

#define NMAX 100000
#define EMAX 1700000
#define DMAX 64
#define SCAN_CHUNK 512

// ---------------- scratch (device globals; no allocation allowed) ----------
__device__ int   g_is64;
__device__ int   g_cnt[NMAX];
__device__ int   g_off[NMAX + 1];
__device__ int   g_part[1024];
__device__ int   g_esrc[EMAX];
__device__ float g_e[EMAX];
__device__ __align__(16) __nv_bfloat16 g_h[(size_t)NMAX * DMAX];   // gather source (bf16)
__device__ __align__(16) float g_bufA[(size_t)NMAX * DMAX];
__device__ __align__(16) float g_bufB[(size_t)NMAX * DMAX];
__device__ float g_as[NMAX];
__device__ float g_ad[NMAX];

__device__ __forceinline__ uint32_t pack_bf2(float a, float b) {
    __nv_bfloat162 v = __floats2bfloat162_rn(a, b);
    return *reinterpret_cast<uint32_t*>(&v);
}

// ---------------- dtype detection ----------------
__global__ void detect_kernel(const unsigned int* __restrict__ w) {
    if (threadIdx.x != 0 || blockIdx.x != 0) return;
    int ok64 = 1;
#pragma unroll
    for (int i = 1; i < 128; i += 2) ok64 &= (w[i] == 0u);
    g_is64 = ok64;
}

__device__ __forceinline__ int load_idx(const void* eiv, long long pos) {
    if (g_is64) return (int)((const long long*)eiv)[pos];
    return ((const int*)eiv)[pos];
}

__device__ __forceinline__ int clampN(int v, int N) {
    return (v < 0) ? 0 : (v >= N ? N - 1 : v);
}

// ---------------- CSR build ----------------
__global__ void zero_cnt_kernel(int N) {
    int i = blockIdx.x * blockDim.x + threadIdx.x;
    if (i < N) g_cnt[i] = 0;
}

__global__ void hist_kernel(const void* __restrict__ eiv, int E, int Etot, int N) {
    int i = blockIdx.x * blockDim.x + threadIdx.x;
    if (i >= Etot) return;
    int d = (i < E) ? clampN(load_idx(eiv, (long long)E + i), N) : (i - E);
    atomicAdd(&g_cnt[d], 1);
}

__global__ void scan_reduce_kernel(int N) {
    __shared__ int sh[256];
    int b = blockIdx.x, t = threadIdx.x;
    int i0 = b * SCAN_CHUNK + t * 2;
    int s = 0;
    if (i0     < N) s += g_cnt[i0];
    if (i0 + 1 < N) s += g_cnt[i0 + 1];
    sh[t] = s;
    __syncthreads();
#pragma unroll
    for (int o = 128; o; o >>= 1) {
        if (t < o) sh[t] += sh[t + o];
        __syncthreads();
    }
    if (t == 0) g_part[b] = sh[0];
}

__global__ void scan_partials_kernel(int B, int N) {
    __shared__ int sh[1024];
    int t = threadIdx.x;
    int v = (t < B) ? g_part[t] : 0;
    sh[t] = v;
    __syncthreads();
#pragma unroll
    for (int o = 1; o < 1024; o <<= 1) {
        int u = (t >= o) ? sh[t - o] : 0;
        __syncthreads();
        sh[t] += u;
        __syncthreads();
    }
    if (t < B) g_part[t] = sh[t] - v;
    if (t == 1023) g_off[N] = sh[1023];
}

__global__ void scan_final_kernel(int N) {
    __shared__ int sh[256];
    int b = blockIdx.x, t = threadIdx.x;
    int i0 = b * SCAN_CHUNK + t * 2;
    int c0 = (i0     < N) ? g_cnt[i0]     : 0;
    int c1 = (i0 + 1 < N) ? g_cnt[i0 + 1] : 0;
    int s = c0 + c1;
    sh[t] = s;
    __syncthreads();
#pragma unroll
    for (int o = 1; o < 256; o <<= 1) {
        int u = (t >= o) ? sh[t - o] : 0;
        __syncthreads();
        sh[t] += u;
        __syncthreads();
    }
    int base = g_part[b] + sh[t] - s;
    if (i0 < N)     { g_off[i0]     = base;      g_cnt[i0]     = base; }
    if (i0 + 1 < N) { g_off[i0 + 1] = base + c0; g_cnt[i0 + 1] = base + c0; }
}

__global__ void scatter_kernel(const void* __restrict__ eiv, int E, int Etot, int N) {
    int i = blockIdx.x * blockDim.x + threadIdx.x;
    if (i >= Etot) return;
    int s, d;
    if (i < E) {
        s = clampN(load_idx(eiv, i), N);
        d = clampN(load_idx(eiv, (long long)E + i), N);
    } else {
        s = d = i - E;
    }
    int p = atomicAdd(&g_cnt[d], 1);
    if (p >= 0 && p < EMAX) g_esrc[p] = s;
}

// ---------------- GEMM (128x64 tile, 8x4/thread, double-buffered) ----------
// h(bf16) = X @ W ; also g_as/g_ad = h @ a_s/a_d (fp32 accumulators)
__global__ __launch_bounds__(256) void gemm_kernel(
    const float* __restrict__ Xext, int sel_in,
    const float* __restrict__ W,
    const float* __restrict__ a_s, const float* __restrict__ a_d,
    int N, int F, int D, int relu_in)
{
    const float* X = (sel_in == 0) ? Xext
                   : (sel_in == 1 ? (const float*)g_bufA : (const float*)g_bufB);
    __shared__ __align__(16) float xs[2][16][132];
    __shared__ __align__(16) float ws[2][16][64];
    __shared__ float as_s[64], ad_s[64];
    int tid  = threadIdx.x;
    int row0 = blockIdx.x * 128;
    int tr = tid >> 4, tc = tid & 15;
    float acc[8][4] = {};
    int f0 = tid * 2;
    int lrow0 = f0 >> 2, lq0 = f0 & 3;
    int lrow1 = (f0 + 1) >> 2, lq1 = (f0 + 1) & 3;
    int wcol = tid & 63, wk0 = (tid >> 6) << 2;
    int gn0 = row0 + lrow0, gn1 = row0 + lrow1;
    const float4* Xr0 = reinterpret_cast<const float4*>(X + (size_t)gn0 * F);
    const float4* Xr1 = reinterpret_cast<const float4*>(X + (size_t)gn1 * F);

    if (tid < 64) {
        as_s[tid] = (tid < D) ? a_s[tid] : 0.f;
        ad_s[tid] = (tid < D) ? a_d[tid] : 0.f;
    }

    int T = F >> 4;
    float4 xv0, xv1;
    float wv[4];
    {
        xv0 = make_float4(0.f,0.f,0.f,0.f); xv1 = xv0;
        if (gn0 < N) xv0 = Xr0[lq0];
        if (gn1 < N) xv1 = Xr1[lq1];
#pragma unroll
        for (int j = 0; j < 4; j++)
            wv[j] = (wcol < D) ? W[(size_t)(wk0 + j) * D + wcol] : 0.f;
    }

    for (int t = 0; t < T; t++) {
        int cur = t & 1;
        if (relu_in) {
            xv0.x = fmaxf(xv0.x, 0.f); xv0.y = fmaxf(xv0.y, 0.f);
            xv0.z = fmaxf(xv0.z, 0.f); xv0.w = fmaxf(xv0.w, 0.f);
            xv1.x = fmaxf(xv1.x, 0.f); xv1.y = fmaxf(xv1.y, 0.f);
            xv1.z = fmaxf(xv1.z, 0.f); xv1.w = fmaxf(xv1.w, 0.f);
        }
        xs[cur][lq0 * 4 + 0][lrow0] = xv0.x;
        xs[cur][lq0 * 4 + 1][lrow0] = xv0.y;
        xs[cur][lq0 * 4 + 2][lrow0] = xv0.z;
        xs[cur][lq0 * 4 + 3][lrow0] = xv0.w;
        xs[cur][lq1 * 4 + 0][lrow1] = xv1.x;
        xs[cur][lq1 * 4 + 1][lrow1] = xv1.y;
        xs[cur][lq1 * 4 + 2][lrow1] = xv1.z;
        xs[cur][lq1 * 4 + 3][lrow1] = xv1.w;
#pragma unroll
        for (int j = 0; j < 4; j++)
            ws[cur][wk0 + j][wcol] = wv[j];
        __syncthreads();

        if (t + 1 < T) {
            int k1 = (t + 1) << 4;
            xv0 = make_float4(0.f,0.f,0.f,0.f); xv1 = xv0;
            if (gn0 < N) xv0 = Xr0[(k1 >> 2) + lq0];
            if (gn1 < N) xv1 = Xr1[(k1 >> 2) + lq1];
#pragma unroll
            for (int j = 0; j < 4; j++)
                wv[j] = (wcol < D) ? W[(size_t)(k1 + wk0 + j) * D + wcol] : 0.f;
        }

#pragma unroll
        for (int k = 0; k < 16; k++) {
            float4 a04 = *(const float4*)&xs[cur][k][tr * 8];
            float4 a48 = *(const float4*)&xs[cur][k][tr * 8 + 4];
            float4 b   = *(const float4*)&ws[cur][k][tc * 4];
            acc[0][0] += a04.x * b.x; acc[0][1] += a04.x * b.y; acc[0][2] += a04.x * b.z; acc[0][3] += a04.x * b.w;
            acc[1][0] += a04.y * b.x; acc[1][1] += a04.y * b.y; acc[1][2] += a04.y * b.z; acc[1][3] += a04.y * b.w;
            acc[2][0] += a04.z * b.x; acc[2][1] += a04.z * b.y; acc[2][2] += a04.z * b.z; acc[2][3] += a04.z * b.w;
            acc[3][0] += a04.w * b.x; acc[3][1] += a04.w * b.y; acc[3][2] += a04.w * b.z; acc[3][3] += a04.w * b.w;
            acc[4][0] += a48.x * b.x; acc[4][1] += a48.x * b.y; acc[4][2] += a48.x * b.z; acc[4][3] += a48.x * b.w;
            acc[5][0] += a48.y * b.x; acc[5][1] += a48.y * b.y; acc[5][2] += a48.y * b.z; acc[5][3] += a48.y * b.w;
            acc[6][0] += a48.z * b.x; acc[6][1] += a48.z * b.y; acc[6][2] += a48.z * b.z; acc[6][3] += a48.z * b.w;
            acc[7][0] += a48.w * b.x; acc[7][1] += a48.w * b.y; acc[7][2] += a48.w * b.z; acc[7][3] += a48.w * b.w;
        }
        __syncthreads();
    }

    float sdot[8] = {}, ddot[8] = {};
    int c0 = tc * 4;
#pragma unroll
    for (int i = 0; i < 8; i++) {
        int n = row0 + tr * 8 + i;
        bool ok = (n < N);
        if (ok && c0 < D) {   // D % 4 == 0, so a full uint2 (4 bf16) fits
            uint2 hp = make_uint2(pack_bf2(acc[i][0], acc[i][1]),
                                  pack_bf2(acc[i][2], acc[i][3]));
            *reinterpret_cast<uint2*>(&g_h[(size_t)n * D + c0]) = hp;
        }
#pragma unroll
        for (int j = 0; j < 4; j++) {
            float w = (c0 + j < D) ? acc[i][j] : 0.f;
            sdot[i] += w * as_s[c0 + j];
            ddot[i] += w * ad_s[c0 + j];
        }
    }
#pragma unroll
    for (int o = 8; o; o >>= 1) {
#pragma unroll
        for (int i = 0; i < 8; i++) {
            sdot[i] += __shfl_xor_sync(0xffffffffu, sdot[i], o);
            ddot[i] += __shfl_xor_sync(0xffffffffu, ddot[i], o);
        }
    }
    if (tc == 0) {
#pragma unroll
        for (int i = 0; i < 8; i++) {
            int n = row0 + tr * 8 + i;
            if (n < N) { g_as[n] = sdot[i]; g_ad[n] = ddot[i]; }
        }
    }
}

// ---------------- fused segment softmax + aggregation (warp per dst) -------
// pass 3: half-warp edge parallelism; gathers bf16 h rows (half the bytes).
__global__ void agg_kernel(float* OUText, int sel_out, int N, int D)
{
    float* OUT = (sel_out == 0) ? OUText : (sel_out == 1 ? g_bufA : g_bufB);
    int warp = (blockIdx.x * blockDim.x + threadIdx.x) >> 5;
    int lane = threadIdx.x & 31;
    int nw = (gridDim.x * blockDim.x) >> 5;
    int half = lane >> 4;          // 0 or 1
    int hl   = lane & 15;          // lane within half
    int c0   = hl * 4;
    bool act = (c0 < D);

    for (int n = warp; n < N; n += nw) {
        int beg = g_off[n], end = g_off[n + 1];
        float adn = g_ad[n];

        // pass 1: ex = exp(leaky_relu(as[src]+ad[n])), cache + sum (fp32)
        float sum = 0.f;
        for (int p = beg + lane; p < end; p += 32) {
            float v = g_as[g_esrc[p]] + adn;
            v = (v > 0.f) ? v : 0.2f * v;
            float ex = __expf(v);
            g_e[p] = ex;
            sum += ex;
        }
#pragma unroll
        for (int o = 16; o; o >>= 1) sum += __shfl_xor_sync(0xffffffffu, sum, o);
        float inv = 1.f / (sum + 1e-16f);

        // pass 3: halves handle alternating edges; lane covers 4 cols (bf16)
        float4 acc = make_float4(0.f, 0.f, 0.f, 0.f);
#pragma unroll 2
        for (int p = beg + half; p < end; p += 2) {
            float a = g_e[p] * inv;      // broadcast within half
            int s = g_esrc[p];
            if (act) {
                uint2 hv = *reinterpret_cast<const uint2*>(&g_h[(size_t)s * D + c0]);
                float2 f0 = __bfloat1622float2(*reinterpret_cast<__nv_bfloat162*>(&hv.x));
                float2 f1 = __bfloat1622float2(*reinterpret_cast<__nv_bfloat162*>(&hv.y));
                acc.x += a * f0.x;
                acc.y += a * f0.y;
                acc.z += a * f1.x;
                acc.w += a * f1.y;
            }
        }
        acc.x += __shfl_xor_sync(0xffffffffu, acc.x, 16);
        acc.y += __shfl_xor_sync(0xffffffffu, acc.y, 16);
        acc.z += __shfl_xor_sync(0xffffffffu, acc.z, 16);
        acc.w += __shfl_xor_sync(0xffffffffu, acc.w, 16);
        if (half == 0 && act)
            *reinterpret_cast<float4*>(&OUT[(size_t)n * D + c0]) = acc;
    }
}

// ---------------- launch ----------------
extern "C" void kernel_launch(void* const* d_in, const int* in_sizes, int n_in,
                              void* d_out, int out_size)
{
    const float* x     = (const float*)d_in[0];
    const void*  ei    = d_in[1];
    const float* W0    = (const float*)d_in[2];
    const float* asrc0 = (const float*)d_in[3];
    const float* adst0 = (const float*)d_in[4];
    const float* W1    = (const float*)d_in[5];
    const float* asrc1 = (const float*)d_in[6];
    const float* adst1 = (const float*)d_in[7];
    const float* W2    = (const float*)d_in[8];
    const float* asrc2 = (const float*)d_in[9];
    const float* adst2 = (const float*)d_in[10];

    int H    = in_sizes[3];            // 64
    int C    = in_sizes[9];            // 40
    int Fin  = in_sizes[2] / H;        // 256
    int N    = in_sizes[0] / Fin;      // 100000
    int E    = in_sizes[1] / 2;        // 1600000
    int Etot = E + N;
    int SB   = (N + SCAN_CHUNK - 1) / SCAN_CHUNK;

    static cudaStream_t s2 = nullptr;
    static cudaEvent_t ev_fork = nullptr, ev_csr = nullptr;
    if (!s2) {
        cudaStreamCreateWithFlags(&s2, cudaStreamNonBlocking);
        cudaEventCreateWithFlags(&ev_fork, cudaEventDisableTiming);
        cudaEventCreateWithFlags(&ev_csr, cudaEventDisableTiming);
    }

    int gemm_blocks = (N + 127) / 128;
    int wg_blocks   = (N + 7) / 8;

    // fork: CSR build on s2, concurrent with gemm0 on the main stream
    cudaEventRecord(ev_fork, 0);
    cudaStreamWaitEvent(s2, ev_fork, 0);

    detect_kernel<<<1, 32, 0, s2>>>((const unsigned int*)ei);
    zero_cnt_kernel<<<(N + 255) / 256, 256, 0, s2>>>(N);
    hist_kernel<<<(Etot + 255) / 256, 256, 0, s2>>>(ei, E, Etot, N);
    scan_reduce_kernel<<<SB, 256, 0, s2>>>(N);
    scan_partials_kernel<<<1, 1024, 0, s2>>>(SB, N);
    scan_final_kernel<<<SB, 256, 0, s2>>>(N);
    scatter_kernel<<<(Etot + 255) / 256, 256, 0, s2>>>(ei, E, Etot, N);
    cudaEventRecord(ev_csr, s2);

    // layer 0 GEMM (concurrent with CSR build)
    gemm_kernel<<<gemm_blocks, 256>>>(x, 0, W0, asrc0, adst0, N, Fin, H, 0);

    cudaStreamWaitEvent(0, ev_csr, 0);
    agg_kernel<<<wg_blocks, 256>>>(nullptr, 1, N, H);

    gemm_kernel<<<gemm_blocks, 256>>>(nullptr, 1, W1, asrc1, adst1, N, H, H, 1);
    agg_kernel<<<wg_blocks, 256>>>(nullptr, 2, N, H);

    gemm_kernel<<<gemm_blocks, 256>>>(nullptr, 2, W2, asrc2, adst2, N, H, C, 1);
    agg_kernel<<<wg_blocks, 256>>>((float*)d_out, 0, N, C);
}

// round 15
// speedup vs baseline: 1.2008x; 1.0430x over previous
#include <cuda_runtime.h>
#include <math.h>

#define NMAX 100000
#define EMAX 1700000
#define DMAX 64
#define SCAN_CHUNK 512

// ---------------- scratch (device globals; no allocation allowed) ----------
__device__ int   g_is64;
__device__ int   g_cnt[NMAX];
__device__ int   g_off[NMAX + 1];
__device__ int   g_part[1024];
__device__ int   g_esrc[EMAX];
__device__ float g_e[EMAX];
__device__ __align__(16) float g_hA[(size_t)NMAX * DMAX];
__device__ __align__(16) float g_hB[(size_t)NMAX * DMAX];
__device__ __align__(16) float g_buf[(size_t)NMAX * DMAX];
__device__ float g_dsA[NMAX], g_ddA[NMAX];
__device__ float g_dsB[NMAX], g_ddB[NMAX];

// ---------------- dtype detection ----------------
__global__ void detect_kernel(const unsigned int* __restrict__ w) {
    if (threadIdx.x != 0 || blockIdx.x != 0) return;
    int ok64 = 1;
#pragma unroll
    for (int i = 1; i < 128; i += 2) ok64 &= (w[i] == 0u);
    g_is64 = ok64;
}

__device__ __forceinline__ int load_idx(const void* eiv, long long pos) {
    if (g_is64) return (int)((const long long*)eiv)[pos];
    return ((const int*)eiv)[pos];
}

__device__ __forceinline__ int clampN(int v, int N) {
    return (v < 0) ? 0 : (v >= N ? N - 1 : v);
}

// ---------------- CSR build ----------------
__global__ void zero_cnt_kernel(int N) {
    int i = blockIdx.x * blockDim.x + threadIdx.x;
    if (i < N) g_cnt[i] = 0;
}

__global__ void hist_kernel(const void* __restrict__ eiv, int E, int Etot, int N) {
    int i = blockIdx.x * blockDim.x + threadIdx.x;
    if (i >= Etot) return;
    int d = (i < E) ? clampN(load_idx(eiv, (long long)E + i), N) : (i - E);
    atomicAdd(&g_cnt[d], 1);
}

__global__ void scan_reduce_kernel(int N) {
    __shared__ int sh[256];
    int b = blockIdx.x, t = threadIdx.x;
    int i0 = b * SCAN_CHUNK + t * 2;
    int s = 0;
    if (i0     < N) s += g_cnt[i0];
    if (i0 + 1 < N) s += g_cnt[i0 + 1];
    sh[t] = s;
    __syncthreads();
#pragma unroll
    for (int o = 128; o; o >>= 1) {
        if (t < o) sh[t] += sh[t + o];
        __syncthreads();
    }
    if (t == 0) g_part[b] = sh[0];
}

__global__ void scan_partials_kernel(int B, int N) {
    __shared__ int sh[1024];
    int t = threadIdx.x;
    int v = (t < B) ? g_part[t] : 0;
    sh[t] = v;
    __syncthreads();
#pragma unroll
    for (int o = 1; o < 1024; o <<= 1) {
        int u = (t >= o) ? sh[t - o] : 0;
        __syncthreads();
        sh[t] += u;
        __syncthreads();
    }
    if (t < B) g_part[t] = sh[t] - v;
    if (t == 1023) g_off[N] = sh[1023];
}

__global__ void scan_final_kernel(int N) {
    __shared__ int sh[256];
    int b = blockIdx.x, t = threadIdx.x;
    int i0 = b * SCAN_CHUNK + t * 2;
    int c0 = (i0     < N) ? g_cnt[i0]     : 0;
    int c1 = (i0 + 1 < N) ? g_cnt[i0 + 1] : 0;
    int s = c0 + c1;
    sh[t] = s;
    __syncthreads();
#pragma unroll
    for (int o = 1; o < 256; o <<= 1) {
        int u = (t >= o) ? sh[t - o] : 0;
        __syncthreads();
        sh[t] += u;
        __syncthreads();
    }
    int base = g_part[b] + sh[t] - s;
    if (i0 < N)     { g_off[i0]     = base;      g_cnt[i0]     = base; }
    if (i0 + 1 < N) { g_off[i0 + 1] = base + c0; g_cnt[i0 + 1] = base + c0; }
}

__global__ void scatter_kernel(const void* __restrict__ eiv, int E, int Etot, int N) {
    int i = blockIdx.x * blockDim.x + threadIdx.x;
    if (i >= Etot) return;
    int s, d;
    if (i < E) {
        s = clampN(load_idx(eiv, i), N);
        d = clampN(load_idx(eiv, (long long)E + i), N);
    } else {
        s = d = i - E;
    }
    int p = atomicAdd(&g_cnt[d], 1);
    if (p >= 0 && p < EMAX) g_esrc[p] = s;
}

// ---------------- GEMM (128x64 tile, 8x4/thread, double-buffered smem) -----
// Hout[nbeg..nend) = X @ W (relu(X) if relu_in); dots into as_out/ad_out.
__global__ __launch_bounds__(256) void gemm_kernel(
    const float* __restrict__ X,
    const float* __restrict__ W,
    const float* __restrict__ a_s, const float* __restrict__ a_d,
    float* __restrict__ Hout,
    float* __restrict__ as_out, float* __restrict__ ad_out,
    int nbeg, int nend, int F, int D, int relu_in)
{
    __shared__ __align__(16) float xs[2][16][132];
    __shared__ __align__(16) float ws[2][16][64];
    __shared__ float as_s[64], ad_s[64];
    int tid  = threadIdx.x;
    int row0 = nbeg + blockIdx.x * 128;
    int tr = tid >> 4, tc = tid & 15;
    float acc[8][4] = {};
    int f0 = tid * 2;
    int lrow0 = f0 >> 2, lq0 = f0 & 3;
    int lrow1 = (f0 + 1) >> 2, lq1 = (f0 + 1) & 3;
    int wcol = tid & 63, wk0 = (tid >> 6) << 2;
    int gn0 = row0 + lrow0, gn1 = row0 + lrow1;
    const float4* Xr0 = reinterpret_cast<const float4*>(X + (size_t)gn0 * F);
    const float4* Xr1 = reinterpret_cast<const float4*>(X + (size_t)gn1 * F);

    if (tid < 64) {
        as_s[tid] = (tid < D) ? a_s[tid] : 0.f;
        ad_s[tid] = (tid < D) ? a_d[tid] : 0.f;
    }

    int T = F >> 4;
    float4 xv0, xv1;
    float wv[4];
    {
        xv0 = make_float4(0.f,0.f,0.f,0.f); xv1 = xv0;
        if (gn0 < nend) xv0 = Xr0[lq0];
        if (gn1 < nend) xv1 = Xr1[lq1];
#pragma unroll
        for (int j = 0; j < 4; j++)
            wv[j] = (wcol < D) ? W[(size_t)(wk0 + j) * D + wcol] : 0.f;
    }

    for (int t = 0; t < T; t++) {
        int cur = t & 1;
        if (relu_in) {
            xv0.x = fmaxf(xv0.x, 0.f); xv0.y = fmaxf(xv0.y, 0.f);
            xv0.z = fmaxf(xv0.z, 0.f); xv0.w = fmaxf(xv0.w, 0.f);
            xv1.x = fmaxf(xv1.x, 0.f); xv1.y = fmaxf(xv1.y, 0.f);
            xv1.z = fmaxf(xv1.z, 0.f); xv1.w = fmaxf(xv1.w, 0.f);
        }
        xs[cur][lq0 * 4 + 0][lrow0] = xv0.x;
        xs[cur][lq0 * 4 + 1][lrow0] = xv0.y;
        xs[cur][lq0 * 4 + 2][lrow0] = xv0.z;
        xs[cur][lq0 * 4 + 3][lrow0] = xv0.w;
        xs[cur][lq1 * 4 + 0][lrow1] = xv1.x;
        xs[cur][lq1 * 4 + 1][lrow1] = xv1.y;
        xs[cur][lq1 * 4 + 2][lrow1] = xv1.z;
        xs[cur][lq1 * 4 + 3][lrow1] = xv1.w;
#pragma unroll
        for (int j = 0; j < 4; j++)
            ws[cur][wk0 + j][wcol] = wv[j];
        __syncthreads();

        if (t + 1 < T) {
            int k1 = (t + 1) << 4;
            xv0 = make_float4(0.f,0.f,0.f,0.f); xv1 = xv0;
            if (gn0 < nend) xv0 = Xr0[(k1 >> 2) + lq0];
            if (gn1 < nend) xv1 = Xr1[(k1 >> 2) + lq1];
#pragma unroll
            for (int j = 0; j < 4; j++)
                wv[j] = (wcol < D) ? W[(size_t)(k1 + wk0 + j) * D + wcol] : 0.f;
        }

#pragma unroll
        for (int k = 0; k < 16; k++) {
            float4 a04 = *(const float4*)&xs[cur][k][tr * 8];
            float4 a48 = *(const float4*)&xs[cur][k][tr * 8 + 4];
            float4 b   = *(const float4*)&ws[cur][k][tc * 4];
            acc[0][0] += a04.x * b.x; acc[0][1] += a04.x * b.y; acc[0][2] += a04.x * b.z; acc[0][3] += a04.x * b.w;
            acc[1][0] += a04.y * b.x; acc[1][1] += a04.y * b.y; acc[1][2] += a04.y * b.z; acc[1][3] += a04.y * b.w;
            acc[2][0] += a04.z * b.x; acc[2][1] += a04.z * b.y; acc[2][2] += a04.z * b.z; acc[2][3] += a04.z * b.w;
            acc[3][0] += a04.w * b.x; acc[3][1] += a04.w * b.y; acc[3][2] += a04.w * b.z; acc[3][3] += a04.w * b.w;
            acc[4][0] += a48.x * b.x; acc[4][1] += a48.x * b.y; acc[4][2] += a48.x * b.z; acc[4][3] += a48.x * b.w;
            acc[5][0] += a48.y * b.x; acc[5][1] += a48.y * b.y; acc[5][2] += a48.y * b.z; acc[5][3] += a48.y * b.w;
            acc[6][0] += a48.z * b.x; acc[6][1] += a48.z * b.y; acc[6][2] += a48.z * b.z; acc[6][3] += a48.z * b.w;
            acc[7][0] += a48.w * b.x; acc[7][1] += a48.w * b.y; acc[7][2] += a48.w * b.z; acc[7][3] += a48.w * b.w;
        }
        __syncthreads();
    }

    float sdot[8] = {}, ddot[8] = {};
    int c0 = tc * 4;
#pragma unroll
    for (int i = 0; i < 8; i++) {
        int n = row0 + tr * 8 + i;
        bool ok = (n < nend);
#pragma unroll
        for (int j = 0; j < 4; j++) {
            int c = c0 + j;
            if (ok && c < D) Hout[(size_t)n * D + c] = acc[i][j];
            float w = (c < D) ? acc[i][j] : 0.f;
            sdot[i] += w * as_s[c];
            ddot[i] += w * ad_s[c];
        }
    }
#pragma unroll
    for (int o = 8; o; o >>= 1) {
#pragma unroll
        for (int i = 0; i < 8; i++) {
            sdot[i] += __shfl_xor_sync(0xffffffffu, sdot[i], o);
            ddot[i] += __shfl_xor_sync(0xffffffffu, ddot[i], o);
        }
    }
    if (tc == 0) {
#pragma unroll
        for (int i = 0; i < 8; i++) {
            int n = row0 + tr * 8 + i;
            if (n < nend) { as_out[n] = sdot[i]; ad_out[n] = ddot[i]; }
        }
    }
}

// ---------------- fused segment softmax + aggregation (warp per dst) -------
// R10 half-warp form, over node range [nbeg, nend).
__global__ void agg_kernel(
    const float* __restrict__ Hin,
    const float* __restrict__ as_in, const float* __restrict__ ad_in,
    float* __restrict__ OUT,
    int nbeg, int nend, int D)
{
    int warp = (blockIdx.x * blockDim.x + threadIdx.x) >> 5;
    int lane = threadIdx.x & 31;
    int nw = (gridDim.x * blockDim.x) >> 5;
    const float4* H4 = reinterpret_cast<const float4*>(Hin);
    int rowst = D >> 2;
    int half = lane >> 4;
    int hl   = lane & 15;
    int c0   = hl * 4;
    bool act = (c0 < D);

    for (int n = nbeg + warp; n < nend; n += nw) {
        int beg = g_off[n], end = g_off[n + 1];
        float adn = ad_in[n];

        float sum = 0.f;
        for (int p = beg + lane; p < end; p += 32) {
            float v = as_in[g_esrc[p]] + adn;
            v = (v > 0.f) ? v : 0.2f * v;
            float ex = __expf(v);
            g_e[p] = ex;
            sum += ex;
        }
#pragma unroll
        for (int o = 16; o; o >>= 1) sum += __shfl_xor_sync(0xffffffffu, sum, o);
        float inv = 1.f / (sum + 1e-16f);

        float4 acc = make_float4(0.f, 0.f, 0.f, 0.f);
#pragma unroll 2
        for (int p = beg + half; p < end; p += 2) {
            float a = g_e[p] * inv;
            int s = g_esrc[p];
            if (act) {
                float4 h = H4[(size_t)s * rowst + hl];
                acc.x += a * h.x;
                acc.y += a * h.y;
                acc.z += a * h.z;
                acc.w += a * h.w;
            }
        }
        acc.x += __shfl_xor_sync(0xffffffffu, acc.x, 16);
        acc.y += __shfl_xor_sync(0xffffffffu, acc.y, 16);
        acc.z += __shfl_xor_sync(0xffffffffu, acc.z, 16);
        acc.w += __shfl_xor_sync(0xffffffffu, acc.w, 16);
        if (half == 0 && act)
            *reinterpret_cast<float4*>(&OUT[(size_t)n * D + c0]) = acc;
    }
}

// ---------------- launch ----------------
extern "C" void kernel_launch(void* const* d_in, const int* in_sizes, int n_in,
                              void* d_out, int out_size)
{
    const float* x     = (const float*)d_in[0];
    const void*  ei    = d_in[1];
    const float* W0    = (const float*)d_in[2];
    const float* asrc0 = (const float*)d_in[3];
    const float* adst0 = (const float*)d_in[4];
    const float* W1    = (const float*)d_in[5];
    const float* asrc1 = (const float*)d_in[6];
    const float* adst1 = (const float*)d_in[7];
    const float* W2    = (const float*)d_in[8];
    const float* asrc2 = (const float*)d_in[9];
    const float* adst2 = (const float*)d_in[10];

    int H    = in_sizes[3];            // 64
    int C    = in_sizes[9];            // 40
    int Fin  = in_sizes[2] / H;        // 256
    int N    = in_sizes[0] / Fin;      // 100000
    int E    = in_sizes[1] / 2;        // 1600000
    int Etot = E + N;
    int SB   = (N + SCAN_CHUNK - 1) / SCAN_CHUNK;
    int NH   = ((N / 2 + 127) / 128) * 128;   // half split, 128-aligned

    static cudaStream_t s2 = nullptr;
    static cudaEvent_t ev[8];
    static float *hA, *hB, *buf, *dsA, *ddA, *dsB, *ddB;
    if (!s2) {
        cudaStreamCreateWithFlags(&s2, cudaStreamNonBlocking);
        for (int i = 0; i < 8; i++)
            cudaEventCreateWithFlags(&ev[i], cudaEventDisableTiming);
        cudaGetSymbolAddress((void**)&hA,  g_hA);
        cudaGetSymbolAddress((void**)&hB,  g_hB);
        cudaGetSymbolAddress((void**)&buf, g_buf);
        cudaGetSymbolAddress((void**)&dsA, g_dsA);
        cudaGetSymbolAddress((void**)&ddA, g_ddA);
        cudaGetSymbolAddress((void**)&dsB, g_dsB);
        cudaGetSymbolAddress((void**)&ddB, g_ddB);
    }

    int gb_a = (NH + 127) / 128;            // blocks for half A (gemm)
    int gb_b = (N - NH + 127) / 128;        // blocks for half B
    int gb_f = (N + 127) / 128;             // full
    int wb_a = (NH + 7) / 8;                // agg blocks half A
    int wb_b = (N - NH + 7) / 8;
    int wb_f = (N + 7) / 8;

    // fork: CSR build on s2, concurrent with gemm0 on the main stream
    cudaEventRecord(ev[0], 0);
    cudaStreamWaitEvent(s2, ev[0], 0);
    detect_kernel<<<1, 32, 0, s2>>>((const unsigned int*)ei);
    zero_cnt_kernel<<<(N + 255) / 256, 256, 0, s2>>>(N);
    hist_kernel<<<(Etot + 255) / 256, 256, 0, s2>>>(ei, E, Etot, N);
    scan_reduce_kernel<<<SB, 256, 0, s2>>>(N);
    scan_partials_kernel<<<1, 1024, 0, s2>>>(SB, N);
    scan_final_kernel<<<SB, 256, 0, s2>>>(N);
    scatter_kernel<<<(Etot + 255) / 256, 256, 0, s2>>>(ei, E, Etot, N);
    cudaEventRecord(ev[1], s2);

    // layer 0 GEMM (full, concurrent with CSR): x -> hA, dots -> A
    gemm_kernel<<<gb_f, 256>>>(x, W0, asrc0, adst0, hA, dsA, ddA, 0, N, Fin, H, 0);
    cudaStreamWaitEvent(0, ev[1], 0);       // join CSR
    cudaEventRecord(ev[2], 0);              // gemm0 + CSR both done

    // ---- layer 1 (split halves, pipelined across streams) ----
    // main: agg1a -> gemm1a   s2: agg1b -> gemm1b (after ev[2] + agg1a start)
    agg_kernel<<<wb_a, 256>>>(hA, dsA, ddA, buf, 0, NH, H);
    cudaEventRecord(ev[3], 0);
    gemm_kernel<<<gb_a, 256>>>(buf, W1, asrc1, adst1, hB, dsB, ddB, 0, NH, H, H, 1);

    cudaStreamWaitEvent(s2, ev[2], 0);
    cudaStreamWaitEvent(s2, ev[3], 0);      // start after agg1a for overlap w/ gemm1a
    agg_kernel<<<wb_b, 256, 0, s2>>>(hA, dsA, ddA, buf, NH, N, H);
    gemm_kernel<<<gb_b, 256, 0, s2>>>(buf, W1, asrc1, adst1, hB, dsB, ddB, NH, N, H, H, 1);
    cudaEventRecord(ev[4], s2);

    // ---- layer 2 (split halves) ----
    cudaStreamWaitEvent(0, ev[4], 0);       // agg2 needs ALL gemm1 dots + hB
    agg_kernel<<<wb_a, 256>>>(hB, dsB, ddB, buf, 0, NH, H);
    cudaEventRecord(ev[5], 0);
    gemm_kernel<<<gb_a, 256>>>(buf, W2, asrc2, adst2, hA, dsA, ddA, 0, NH, H, C, 1);

    cudaStreamWaitEvent(s2, ev[5], 0);
    agg_kernel<<<wb_b, 256, 0, s2>>>(hB, dsB, ddB, buf, NH, N, H);
    gemm_kernel<<<gb_b, 256, 0, s2>>>(buf, W2, asrc2, adst2, hA, dsA, ddA, NH, N, H, C, 1);
    cudaEventRecord(ev[6], s2);

    // ---- final aggregation (full) ----
    cudaStreamWaitEvent(0, ev[6], 0);
    agg_kernel<<<wb_f, 256>>>(hA, dsA, ddA, (float*)d_out, 0, N, C);
}

// round 16
// speedup vs baseline: 1.2065x; 1.0047x over previous
#include <cuda_runtime.h>
#include <math.h>

#define NMAX 100000
#define EMAX 1700000
#define DMAX 64
#define SCAN_CHUNK 512

// ---------------- scratch (device globals; no allocation allowed) ----------
__device__ int   g_is64;
__device__ int   g_cnt[NMAX];
__device__ int   g_off[NMAX + 1];
__device__ int   g_part[1024];
__device__ int   g_esrc[EMAX];
__device__ __align__(16) float g_h[(size_t)NMAX * DMAX];
__device__ __align__(16) float g_bufA[(size_t)NMAX * DMAX];
__device__ __align__(16) float g_bufB[(size_t)NMAX * DMAX];
__device__ float g_as[NMAX];
__device__ float g_ad[NMAX];

// ---------------- dtype detection ----------------
__global__ void detect_kernel(const unsigned int* __restrict__ w) {
    if (threadIdx.x != 0 || blockIdx.x != 0) return;
    int ok64 = 1;
#pragma unroll
    for (int i = 1; i < 128; i += 2) ok64 &= (w[i] == 0u);
    g_is64 = ok64;
}

__device__ __forceinline__ int load_idx(const void* eiv, long long pos) {
    if (g_is64) return (int)((const long long*)eiv)[pos];
    return ((const int*)eiv)[pos];
}

__device__ __forceinline__ int clampN(int v, int N) {
    return (v < 0) ? 0 : (v >= N ? N - 1 : v);
}

// ---------------- CSR build ----------------
__global__ void zero_cnt_kernel(int N) {
    int i = blockIdx.x * blockDim.x + threadIdx.x;
    if (i < N) g_cnt[i] = 0;
}

__global__ void hist_kernel(const void* __restrict__ eiv, int E, int Etot, int N) {
    int i = blockIdx.x * blockDim.x + threadIdx.x;
    if (i >= Etot) return;
    int d = (i < E) ? clampN(load_idx(eiv, (long long)E + i), N) : (i - E);
    atomicAdd(&g_cnt[d], 1);
}

__global__ void scan_reduce_kernel(int N) {
    __shared__ int sh[256];
    int b = blockIdx.x, t = threadIdx.x;
    int i0 = b * SCAN_CHUNK + t * 2;
    int s = 0;
    if (i0     < N) s += g_cnt[i0];
    if (i0 + 1 < N) s += g_cnt[i0 + 1];
    sh[t] = s;
    __syncthreads();
#pragma unroll
    for (int o = 128; o; o >>= 1) {
        if (t < o) sh[t] += sh[t + o];
        __syncthreads();
    }
    if (t == 0) g_part[b] = sh[0];
}

__global__ void scan_partials_kernel(int B, int N) {
    __shared__ int sh[1024];
    int t = threadIdx.x;
    int v = (t < B) ? g_part[t] : 0;
    sh[t] = v;
    __syncthreads();
#pragma unroll
    for (int o = 1; o < 1024; o <<= 1) {
        int u = (t >= o) ? sh[t - o] : 0;
        __syncthreads();
        sh[t] += u;
        __syncthreads();
    }
    if (t < B) g_part[t] = sh[t] - v;
    if (t == 1023) g_off[N] = sh[1023];
}

__global__ void scan_final_kernel(int N) {
    __shared__ int sh[256];
    int b = blockIdx.x, t = threadIdx.x;
    int i0 = b * SCAN_CHUNK + t * 2;
    int c0 = (i0     < N) ? g_cnt[i0]     : 0;
    int c1 = (i0 + 1 < N) ? g_cnt[i0 + 1] : 0;
    int s = c0 + c1;
    sh[t] = s;
    __syncthreads();
#pragma unroll
    for (int o = 1; o < 256; o <<= 1) {
        int u = (t >= o) ? sh[t - o] : 0;
        __syncthreads();
        sh[t] += u;
        __syncthreads();
    }
    int base = g_part[b] + sh[t] - s;
    if (i0 < N)     { g_off[i0]     = base;      g_cnt[i0]     = base; }
    if (i0 + 1 < N) { g_off[i0 + 1] = base + c0; g_cnt[i0 + 1] = base + c0; }
}

__global__ void scatter_kernel(const void* __restrict__ eiv, int E, int Etot, int N) {
    int i = blockIdx.x * blockDim.x + threadIdx.x;
    if (i >= Etot) return;
    int s, d;
    if (i < E) {
        s = clampN(load_idx(eiv, i), N);
        d = clampN(load_idx(eiv, (long long)E + i), N);
    } else {
        s = d = i - E;
    }
    int p = atomicAdd(&g_cnt[d], 1);
    if (p >= 0 && p < EMAX) g_esrc[p] = s;
}

// ---------------- GEMM (128x64 tile, 8x4/thread, double-buffered) ----------
// h = X @ W  (X: [N,F], W: [F,D], D<=64, F%16==0); also g_as/g_ad = h @ a_s/a_d
__global__ __launch_bounds__(256) void gemm_kernel(
    const float* __restrict__ Xext, int sel_in,
    const float* __restrict__ W,
    const float* __restrict__ a_s, const float* __restrict__ a_d,
    int N, int F, int D, int relu_in)
{
    const float* X = (sel_in == 0) ? Xext
                   : (sel_in == 1 ? (const float*)g_bufA : (const float*)g_bufB);
    __shared__ __align__(16) float xs[2][16][132];
    __shared__ __align__(16) float ws[2][16][64];
    __shared__ float as_s[64], ad_s[64];
    int tid  = threadIdx.x;
    int row0 = blockIdx.x * 128;
    int tr = tid >> 4, tc = tid & 15;
    float acc[8][4] = {};
    int f0 = tid * 2;
    int lrow0 = f0 >> 2, lq0 = f0 & 3;
    int lrow1 = (f0 + 1) >> 2, lq1 = (f0 + 1) & 3;
    int wcol = tid & 63, wk0 = (tid >> 6) << 2;
    int gn0 = row0 + lrow0, gn1 = row0 + lrow1;
    const float4* Xr0 = reinterpret_cast<const float4*>(X + (size_t)gn0 * F);
    const float4* Xr1 = reinterpret_cast<const float4*>(X + (size_t)gn1 * F);

    if (tid < 64) {
        as_s[tid] = (tid < D) ? a_s[tid] : 0.f;
        ad_s[tid] = (tid < D) ? a_d[tid] : 0.f;
    }

    int T = F >> 4;
    float4 xv0, xv1;
    float wv[4];
    {
        xv0 = make_float4(0.f,0.f,0.f,0.f); xv1 = xv0;
        if (gn0 < N) xv0 = Xr0[lq0];
        if (gn1 < N) xv1 = Xr1[lq1];
#pragma unroll
        for (int j = 0; j < 4; j++)
            wv[j] = (wcol < D) ? W[(size_t)(wk0 + j) * D + wcol] : 0.f;
    }

    for (int t = 0; t < T; t++) {
        int cur = t & 1;
        if (relu_in) {
            xv0.x = fmaxf(xv0.x, 0.f); xv0.y = fmaxf(xv0.y, 0.f);
            xv0.z = fmaxf(xv0.z, 0.f); xv0.w = fmaxf(xv0.w, 0.f);
            xv1.x = fmaxf(xv1.x, 0.f); xv1.y = fmaxf(xv1.y, 0.f);
            xv1.z = fmaxf(xv1.z, 0.f); xv1.w = fmaxf(xv1.w, 0.f);
        }
        xs[cur][lq0 * 4 + 0][lrow0] = xv0.x;
        xs[cur][lq0 * 4 + 1][lrow0] = xv0.y;
        xs[cur][lq0 * 4 + 2][lrow0] = xv0.z;
        xs[cur][lq0 * 4 + 3][lrow0] = xv0.w;
        xs[cur][lq1 * 4 + 0][lrow1] = xv1.x;
        xs[cur][lq1 * 4 + 1][lrow1] = xv1.y;
        xs[cur][lq1 * 4 + 2][lrow1] = xv1.z;
        xs[cur][lq1 * 4 + 3][lrow1] = xv1.w;
#pragma unroll
        for (int j = 0; j < 4; j++)
            ws[cur][wk0 + j][wcol] = wv[j];
        __syncthreads();

        if (t + 1 < T) {
            int k1 = (t + 1) << 4;
            xv0 = make_float4(0.f,0.f,0.f,0.f); xv1 = xv0;
            if (gn0 < N) xv0 = Xr0[(k1 >> 2) + lq0];
            if (gn1 < N) xv1 = Xr1[(k1 >> 2) + lq1];
#pragma unroll
            for (int j = 0; j < 4; j++)
                wv[j] = (wcol < D) ? W[(size_t)(k1 + wk0 + j) * D + wcol] : 0.f;
        }

#pragma unroll
        for (int k = 0; k < 16; k++) {
            float4 a04 = *(const float4*)&xs[cur][k][tr * 8];
            float4 a48 = *(const float4*)&xs[cur][k][tr * 8 + 4];
            float4 b   = *(const float4*)&ws[cur][k][tc * 4];
            acc[0][0] += a04.x * b.x; acc[0][1] += a04.x * b.y; acc[0][2] += a04.x * b.z; acc[0][3] += a04.x * b.w;
            acc[1][0] += a04.y * b.x; acc[1][1] += a04.y * b.y; acc[1][2] += a04.y * b.z; acc[1][3] += a04.y * b.w;
            acc[2][0] += a04.z * b.x; acc[2][1] += a04.z * b.y; acc[2][2] += a04.z * b.z; acc[2][3] += a04.z * b.w;
            acc[3][0] += a04.w * b.x; acc[3][1] += a04.w * b.y; acc[3][2] += a04.w * b.z; acc[3][3] += a04.w * b.w;
            acc[4][0] += a48.x * b.x; acc[4][1] += a48.x * b.y; acc[4][2] += a48.x * b.z; acc[4][3] += a48.x * b.w;
            acc[5][0] += a48.y * b.x; acc[5][1] += a48.y * b.y; acc[5][2] += a48.y * b.z; acc[5][3] += a48.y * b.w;
            acc[6][0] += a48.z * b.x; acc[6][1] += a48.z * b.y; acc[6][2] += a48.z * b.z; acc[6][3] += a48.z * b.w;
            acc[7][0] += a48.w * b.x; acc[7][1] += a48.w * b.y; acc[7][2] += a48.w * b.z; acc[7][3] += a48.w * b.w;
        }
        __syncthreads();
    }

    float sdot[8] = {}, ddot[8] = {};
    int c0 = tc * 4;
#pragma unroll
    for (int i = 0; i < 8; i++) {
        int n = row0 + tr * 8 + i;
        bool ok = (n < N);
#pragma unroll
        for (int j = 0; j < 4; j++) {
            int c = c0 + j;
            if (ok && c < D) g_h[(size_t)n * D + c] = acc[i][j];
            float w = (c < D) ? acc[i][j] : 0.f;
            sdot[i] += w * as_s[c];
            ddot[i] += w * ad_s[c];
        }
    }
#pragma unroll
    for (int o = 8; o; o >>= 1) {
#pragma unroll
        for (int i = 0; i < 8; i++) {
            sdot[i] += __shfl_xor_sync(0xffffffffu, sdot[i], o);
            ddot[i] += __shfl_xor_sync(0xffffffffu, ddot[i], o);
        }
    }
    if (tc == 0) {
#pragma unroll
        for (int i = 0; i < 8; i++) {
            int n = row0 + tr * 8 + i;
            if (n < N) { g_as[n] = sdot[i]; g_ad[n] = ddot[i]; }
        }
    }
}

// ---------------- fused single-sweep softmax + aggregation -----------------
// out[n] = (sum_e exp(lrelu(as[src]+ad[n])) * h[src]) / (sum_e exp(..) + eps)
// One edge sweep: halves of the warp handle alternating edges; each lane
// covers 4 cols; ex computed redundantly per lane (broadcast loads, MUFU).
__global__ void agg_kernel(float* OUText, int sel_out, int N, int D)
{
    float* OUT = (sel_out == 0) ? OUText : (sel_out == 1 ? g_bufA : g_bufB);
    int warp = (blockIdx.x * blockDim.x + threadIdx.x) >> 5;
    int lane = threadIdx.x & 31;
    int nw = (gridDim.x * blockDim.x) >> 5;
    const float4* H4 = reinterpret_cast<const float4*>(g_h);
    int rowst = D >> 2;
    int half = lane >> 4;          // 0 or 1
    int hl   = lane & 15;          // lane within half
    int c0   = hl * 4;
    bool act = (c0 < D);

    for (int n = warp; n < N; n += nw) {
        int beg = g_off[n], end = g_off[n + 1];
        float adn = g_ad[n];

        float4 acc = make_float4(0.f, 0.f, 0.f, 0.f);
        float sum = 0.f;
#pragma unroll 2
        for (int p = beg + half; p < end; p += 2) {
            int s = g_esrc[p];                  // broadcast within half
            float v = g_as[s] + adn;            // broadcast within half
            v = (v > 0.f) ? v : 0.2f * v;
            float ex = __expf(v);
            sum += ex;
            if (act) {
                float4 h = H4[(size_t)s * rowst + hl];
                acc.x += ex * h.x;
                acc.y += ex * h.y;
                acc.z += ex * h.z;
                acc.w += ex * h.w;
            }
        }
        // combine halves (each lane of a half holds the full half-sum)
        sum   += __shfl_xor_sync(0xffffffffu, sum, 16);
        acc.x += __shfl_xor_sync(0xffffffffu, acc.x, 16);
        acc.y += __shfl_xor_sync(0xffffffffu, acc.y, 16);
        acc.z += __shfl_xor_sync(0xffffffffu, acc.z, 16);
        acc.w += __shfl_xor_sync(0xffffffffu, acc.w, 16);
        if (half == 0 && act) {
            float inv = 1.f / (sum + 1e-16f);
            acc.x *= inv; acc.y *= inv; acc.z *= inv; acc.w *= inv;
            *reinterpret_cast<float4*>(&OUT[(size_t)n * D + c0]) = acc;
        }
    }
}

// ---------------- launch ----------------
extern "C" void kernel_launch(void* const* d_in, const int* in_sizes, int n_in,
                              void* d_out, int out_size)
{
    const float* x     = (const float*)d_in[0];
    const void*  ei    = d_in[1];
    const float* W0    = (const float*)d_in[2];
    const float* asrc0 = (const float*)d_in[3];
    const float* adst0 = (const float*)d_in[4];
    const float* W1    = (const float*)d_in[5];
    const float* asrc1 = (const float*)d_in[6];
    const float* adst1 = (const float*)d_in[7];
    const float* W2    = (const float*)d_in[8];
    const float* asrc2 = (const float*)d_in[9];
    const float* adst2 = (const float*)d_in[10];

    int H    = in_sizes[3];            // 64
    int C    = in_sizes[9];            // 40
    int Fin  = in_sizes[2] / H;        // 256
    int N    = in_sizes[0] / Fin;      // 100000
    int E    = in_sizes[1] / 2;        // 1600000
    int Etot = E + N;
    int SB   = (N + SCAN_CHUNK - 1) / SCAN_CHUNK;

    static cudaStream_t s2 = nullptr;
    static cudaEvent_t ev_fork = nullptr, ev_csr = nullptr;
    if (!s2) {
        cudaStreamCreateWithFlags(&s2, cudaStreamNonBlocking);
        cudaEventCreateWithFlags(&ev_fork, cudaEventDisableTiming);
        cudaEventCreateWithFlags(&ev_csr, cudaEventDisableTiming);
    }

    int gemm_blocks = (N + 127) / 128;
    int wg_blocks   = (N + 7) / 8;

    // fork: CSR build on s2, concurrent with gemm0 on the main stream
    cudaEventRecord(ev_fork, 0);
    cudaStreamWaitEvent(s2, ev_fork, 0);

    detect_kernel<<<1, 32, 0, s2>>>((const unsigned int*)ei);
    zero_cnt_kernel<<<(N + 255) / 256, 256, 0, s2>>>(N);
    hist_kernel<<<(Etot + 255) / 256, 256, 0, s2>>>(ei, E, Etot, N);
    scan_reduce_kernel<<<SB, 256, 0, s2>>>(N);
    scan_partials_kernel<<<1, 1024, 0, s2>>>(SB, N);
    scan_final_kernel<<<SB, 256, 0, s2>>>(N);
    scatter_kernel<<<(Etot + 255) / 256, 256, 0, s2>>>(ei, E, Etot, N);
    cudaEventRecord(ev_csr, s2);

    // layer 0 GEMM (concurrent with CSR build)
    gemm_kernel<<<gemm_blocks, 256>>>(x, 0, W0, asrc0, adst0, N, Fin, H, 0);

    cudaStreamWaitEvent(0, ev_csr, 0);
    agg_kernel<<<wg_blocks, 256>>>(nullptr, 1, N, H);

    gemm_kernel<<<gemm_blocks, 256>>>(nullptr, 1, W1, asrc1, adst1, N, H, H, 1);
    agg_kernel<<<wg_blocks, 256>>>(nullptr, 2, N, H);

    gemm_kernel<<<gemm_blocks, 256>>>(nullptr, 2, W2, asrc2, adst2, N, H, C, 1);
    agg_kernel<<<wg_blocks, 256>>>((float*)d_out, 0, N, C);
}